// round 6
// baseline (speedup 1.0000x reference)
#include <cuda_runtime.h>
#include <cuda_bf16.h>
#include <cstdint>

#define B_  4
#define NV_ 4096
#define NT_ 1024
#define TD_ 1024
#define H_  8
#define D_  128

// ------------------------- scratch (device globals) -------------------------
__device__ __align__(256) __nv_bfloat16 g_Vh[(size_t)B_*NV_*TD_];
__device__ __align__(256) __nv_bfloat16 g_Vl[(size_t)B_*NV_*TD_];
__device__ __align__(256) __nv_bfloat16 g_Th[(size_t)B_*NT_*TD_];
__device__ __align__(256) __nv_bfloat16 g_Tl[(size_t)B_*NT_*TD_];
__device__ __align__(256) __nv_bfloat16 g_Wh[(size_t)TD_*TD_];
__device__ __align__(256) __nv_bfloat16 g_Wl[(size_t)TD_*TD_];
__device__ __align__(256) __nv_bfloat16 g_Kh[(size_t)B_*NV_*TD_];
__device__ __align__(256) __nv_bfloat16 g_Kl[(size_t)B_*NV_*TD_];

// ------------------------------- helpers ------------------------------------
__device__ __forceinline__ uint32_t smem_u32(const void* p){
    uint32_t a;
    asm("{ .reg .u64 t; cvta.to.shared.u64 t, %1; cvt.u32.u64 %0, t; }" : "=r"(a) : "l"(p));
    return a;
}
__device__ __forceinline__ void cp16(uint32_t dst, const void* src){
    asm volatile("cp.async.cg.shared.global [%0], [%1], 16;" :: "r"(dst), "l"(src));
}
__device__ __forceinline__ void ldsm4(uint32_t* r, uint32_t addr){
    asm volatile("ldmatrix.sync.aligned.m8n8.x4.shared.b16 {%0,%1,%2,%3}, [%4];"
                 : "=r"(r[0]), "=r"(r[1]), "=r"(r[2]), "=r"(r[3]) : "r"(addr));
}
__device__ __forceinline__ void ldsm4t(uint32_t* r, uint32_t addr){
    asm volatile("ldmatrix.sync.aligned.m8n8.x4.trans.shared.b16 {%0,%1,%2,%3}, [%4];"
                 : "=r"(r[0]), "=r"(r[1]), "=r"(r[2]), "=r"(r[3]) : "r"(addr));
}
__device__ __forceinline__ void mma16816(float* c, const uint32_t* a, const uint32_t* b){
    asm volatile("mma.sync.aligned.m16n8k16.row.col.f32.bf16.bf16.f32 "
                 "{%0,%1,%2,%3}, {%4,%5,%6,%7}, {%8,%9}, {%0,%1,%2,%3};"
                 : "+f"(c[0]), "+f"(c[1]), "+f"(c[2]), "+f"(c[3])
                 : "r"(a[0]), "r"(a[1]), "r"(a[2]), "r"(a[3]), "r"(b[0]), "r"(b[1]));
}
__device__ __forceinline__ void split2(float x, float y, uint32_t& hp, uint32_t& lp){
    __nv_bfloat16 h0 = __float2bfloat16(x), h1 = __float2bfloat16(y);
    __nv_bfloat16 l0 = __float2bfloat16(x - __bfloat162float(h0));
    __nv_bfloat16 l1 = __float2bfloat16(y - __bfloat162float(h1));
    hp = (uint32_t)__bfloat16_as_ushort(h0) | ((uint32_t)__bfloat16_as_ushort(h1) << 16);
    lp = (uint32_t)__bfloat16_as_ushort(l0) | ((uint32_t)__bfloat16_as_ushort(l1) << 16);
}

// ------------------------- fp32 -> bf16 hi/lo split --------------------------
__global__ void split_kernel(const float* __restrict__ s, __nv_bfloat16* __restrict__ h,
                             __nv_bfloat16* __restrict__ l, long long n4){
    long long i = (long long)blockIdx.x * blockDim.x + threadIdx.x;
    long long stride = (long long)gridDim.x * blockDim.x;
    for (; i < n4; i += stride){
        float4 f = reinterpret_cast<const float4*>(s)[i];
        uint32_t h0, l0, h1, l1;
        split2(f.x, f.y, h0, l0);
        split2(f.z, f.w, h1, l1);
        reinterpret_cast<uint2*>(h)[i] = make_uint2(h0, h1);
        reinterpret_cast<uint2*>(l)[i] = make_uint2(l0, l1);
    }
}

struct GemmArgs {
    const __nv_bfloat16 *Ah, *Al, *Bh, *Bl;
    const float* Af32;
    float* C; __nv_bfloat16 *Ch, *Cl;
    long long lda, ldb, ldc;
    long long sAb, sAh, sBb, sBh, sCb, sCh;
    int K, HZ;
};

// ---------------------------------------------------------------------------
// 256x128 CTA-tile split-3 GEMM (K-major A and B, pre-split bf16 pairs).
// 8 warps as 4m x 2n, warp tile 64x64. K-chunk 64, 2-stage cp.async ring.
// Per k-iter: 3072 tensor-cyc vs 2048 SMEM-cyc -> tensor-bound.
// ---------------------------------------------------------------------------
#define G2_AH 0
#define G2_AL 32768
#define G2_BH 65536
#define G2_BL 81920
#define G2_STAGE 98304
#define SMEM_G2 (2*G2_STAGE)

__global__ void __launch_bounds__(256, 1) gemm256(GemmArgs g){
    extern __shared__ char smem[];
    const uint32_t sb = smem_u32(smem);
    const int tid = threadIdx.x;
    const int lane = tid & 31, wid = tid >> 5;
    const int wm = wid >> 1, wn = wid & 1;

    const int zb = blockIdx.z / g.HZ, zh = blockIdx.z % g.HZ;
    const long long m0 = (long long)blockIdx.x << 8;
    const long long n0 = (long long)blockIdx.y << 7;
    const long long aoff = (long long)zb*g.sAb + (long long)zh*g.sAh + m0*g.lda;
    const __nv_bfloat16* Ah = g.Ah + aoff;
    const __nv_bfloat16* Al = g.Al + aoff;
    const long long boff = (long long)zb*g.sBb + (long long)zh*g.sBh + n0*g.ldb;
    const __nv_bfloat16* Bh = g.Bh + boff;
    const __nv_bfloat16* Bl = g.Bl + boff;

    float acc[4][8][4];
    #pragma unroll
    for (int a = 0; a < 4; ++a)
        #pragma unroll
        for (int b = 0; b < 8; ++b)
            #pragma unroll
            for (int c = 0; c < 4; ++c) acc[a][b][c] = 0.f;

    const int nkt = g.K >> 6;

    auto load_stage = [&](int S, int kt2){
        const uint32_t sbs = sb + (uint32_t)S * G2_STAGE;
        const long long K0 = (long long)kt2 << 6;
        const int r0 = tid >> 3, gc = tid & 7;
        #pragma unroll
        for (int i = 0; i < 8; ++i){               // A: 256 rows
            int row = r0 + (i << 5);
            uint32_t off = (uint32_t)(row << 7) + (uint32_t)((gc ^ (row & 7)) << 4);
            long long ea = (long long)row * g.lda + K0 + (gc << 3);
            cp16(sbs + G2_AH + off, Ah + ea);
            cp16(sbs + G2_AL + off, Al + ea);
        }
        #pragma unroll
        for (int i = 0; i < 4; ++i){               // B: 128 rows
            int row = r0 + (i << 5);
            uint32_t off = (uint32_t)(row << 7) + (uint32_t)((gc ^ (row & 7)) << 4);
            long long eb = (long long)row * g.ldb + K0 + (gc << 3);
            cp16(sbs + G2_BH + off, Bh + eb);
            cp16(sbs + G2_BL + off, Bl + eb);
        }
    };

    load_stage(0, 0);
    asm volatile("cp.async.commit_group;" ::: "memory");

    for (int kt = 0; kt < nkt; ++kt){
        if (kt + 1 < nkt) load_stage((kt + 1) & 1, kt + 1);
        asm volatile("cp.async.commit_group;" ::: "memory");
        asm volatile("cp.async.wait_group 1;" ::: "memory");
        __syncthreads();

        const uint32_t st = sb + (uint32_t)(kt & 1) * G2_STAGE;
        #pragma unroll
        for (int s16 = 0; s16 < 4; ++s16){
            uint32_t aH[4][4], aL[4][4];
            const int arow0 = (wm << 6) + (lane & 15);
            const int ahalf = lane >> 4;
            #pragma unroll
            for (int mb = 0; mb < 4; ++mb){
                int row = arow0 + (mb << 4);
                uint32_t gc = (uint32_t)(((s16 << 1) + ahalf) ^ (row & 7));
                uint32_t ad = st + (uint32_t)(row << 7) + (gc << 4);
                ldsm4(aH[mb], ad + G2_AH);
                ldsm4(aL[mb], ad + G2_AL);
            }
            uint32_t bH[8][2], bL[8][2];
            const int brow_ = (lane & 7) + ((lane >> 4) << 3);
            const int bhalf = (lane >> 3) & 1;
            #pragma unroll
            for (int bg = 0; bg < 4; ++bg){
                int row = (wn << 6) + (bg << 4) + brow_;
                uint32_t gc = (uint32_t)(((s16 << 1) + bhalf) ^ (row & 7));
                uint32_t bd = st + (uint32_t)(row << 7) + (gc << 4);
                uint32_t rh[4], rl[4];
                ldsm4(rh, bd + G2_BH);
                ldsm4(rl, bd + G2_BL);
                bH[bg*2+0][0] = rh[0]; bH[bg*2+0][1] = rh[1];
                bH[bg*2+1][0] = rh[2]; bH[bg*2+1][1] = rh[3];
                bL[bg*2+0][0] = rl[0]; bL[bg*2+0][1] = rl[1];
                bL[bg*2+1][0] = rl[2]; bL[bg*2+1][1] = rl[3];
            }
            #pragma unroll
            for (int mb = 0; mb < 4; ++mb)
                #pragma unroll
                for (int nb = 0; nb < 8; ++nb){
                    mma16816(acc[mb][nb], aH[mb], bH[nb]);
                    mma16816(acc[mb][nb], aH[mb], bL[nb]);
                    mma16816(acc[mb][nb], aL[mb], bH[nb]);
                }
        }
        __syncthreads();
    }

    // ---- epilogue ----
    const int trow = lane >> 2, tcol = (lane & 3) << 1;
    const long long cbase = (long long)zb*g.sCb + (long long)zh*g.sCh;
    #pragma unroll
    for (int mb = 0; mb < 4; ++mb){
        #pragma unroll
        for (int nb = 0; nb < 8; ++nb){
            long long r0 = m0 + (wm << 6) + (mb << 4) + trow;
            long long cc = n0 + (wn << 6) + (nb << 3) + tcol;
            float* a4 = acc[mb][nb];
            if (g.C){
                *reinterpret_cast<float2*>(g.C + cbase + r0*g.ldc + cc) = make_float2(a4[0], a4[1]);
                *reinterpret_cast<float2*>(g.C + cbase + (r0+8)*g.ldc + cc) = make_float2(a4[2], a4[3]);
            } else {
                uint32_t hp, lp;
                split2(a4[0], a4[1], hp, lp);
                *reinterpret_cast<uint32_t*>(g.Ch + cbase + r0*g.ldc + cc) = hp;
                *reinterpret_cast<uint32_t*>(g.Cl + cbase + r0*g.ldc + cc) = lp;
                split2(a4[2], a4[3], hp, lp);
                *reinterpret_cast<uint32_t*>(g.Ch + cbase + (r0+8)*g.ldc + cc) = hp;
                *reinterpret_cast<uint32_t*>(g.Cl + cbase + (r0+8)*g.ldc + cc) = lp;
            }
        }
    }
}

// ---------------------------------------------------------------------------
// 128x128 TRANSB kernel (GEMM3): A fp32 split on the fly, B N-major via
// ldmatrix.trans. 8 warps 2m x 4n, warp tile 64x32, 3-stage ring.
// ---------------------------------------------------------------------------
#define T_AH 0
#define T_AL 16384
#define T_BH 32768
#define T_BL 49152
#define STAGE 65536
#define SMEM_GEMM (3*STAGE)

__global__ void __launch_bounds__(256, 1) gemm_transb(GemmArgs g){
    extern __shared__ char smem[];
    const uint32_t sb = smem_u32(smem);
    const int tid = threadIdx.x;
    const int lane = tid & 31, wid = tid >> 5;
    const int wm = wid >> 2, wn = wid & 3;

    const int zb = blockIdx.z / g.HZ, zh = blockIdx.z % g.HZ;
    const long long m0 = (long long)blockIdx.x << 7;
    const long long n0 = (long long)blockIdx.y << 7;
    const long long aoff = (long long)zb*g.sAb + (long long)zh*g.sAh + m0*g.lda;
    const float* Af32 = g.Af32 + aoff;
    const long long bofs = (long long)zb*g.sBb + (long long)zh*g.sBh + n0;
    const __nv_bfloat16* Bh = g.Bh + bofs;
    const __nv_bfloat16* Bl = g.Bl + bofs;

    float acc[4][4][4];
    #pragma unroll
    for (int a = 0; a < 4; ++a)
        #pragma unroll
        for (int b = 0; b < 4; ++b)
            #pragma unroll
            for (int c = 0; c < 4; ++c) acc[a][b][c] = 0.f;

    const int nkt = g.K >> 6;

    auto loadB = [&](int S, int kt2){
        const uint32_t sbs = sb + (uint32_t)S * STAGE;
        const long long K0 = (long long)kt2 << 6;
        const int r0 = tid >> 4, bc = tid & 15;
        #pragma unroll
        for (int i = 0; i < 4; ++i){
            int row = r0 + (i << 4);
            uint32_t off = (uint32_t)(row << 8) + (uint32_t)((bc ^ (row & 7)) << 4);
            long long eb = (K0 + row) * g.ldb + (bc << 3);
            cp16(sbs + T_BH + off, Bh + eb);
            cp16(sbs + T_BL + off, Bl + eb);
        }
    };
    float4 ra[8];
    auto ldA = [&](int kt2){
        const long long K0 = (long long)kt2 << 6;
        #pragma unroll
        for (int i = 0; i < 8; ++i){
            int lin = tid + (i << 8);
            int row = lin >> 4, c4 = lin & 15;
            ra[i] = *reinterpret_cast<const float4*>(Af32 + (long long)row*g.lda + K0 + (c4 << 2));
        }
    };
    auto stA = [&](int S){
        char* base = smem + (size_t)S * STAGE;
        #pragma unroll
        for (int i = 0; i < 8; ++i){
            int lin = tid + (i << 8);
            int row = lin >> 4, c4 = lin & 15;
            uint32_t h0, l0, h1, l1;
            split2(ra[i].x, ra[i].y, h0, l0);
            split2(ra[i].z, ra[i].w, h1, l1);
            uint32_t off = (uint32_t)(row << 7)
                         + ((uint32_t)((c4 >> 1) ^ (row & 7)) << 4)
                         + ((uint32_t)(c4 & 1) << 3);
            *reinterpret_cast<uint2*>(base + T_AH + off) = make_uint2(h0, h1);
            *reinterpret_cast<uint2*>(base + T_AL + off) = make_uint2(l0, l1);
        }
    };

    ldA(0); stA(0); loadB(0, 0);
    asm volatile("cp.async.commit_group;" ::: "memory");
    if (nkt > 1){ ldA(1); stA(1); loadB(1, 1); }
    asm volatile("cp.async.commit_group;" ::: "memory");
    if (nkt > 2) ldA(2);

    for (int kt = 0; kt < nkt; ++kt){
        asm volatile("cp.async.wait_group 1;" ::: "memory");
        __syncthreads();
        if (kt + 2 < nkt){ stA((kt + 2) % 3); loadB((kt + 2) % 3, kt + 2); }
        asm volatile("cp.async.commit_group;" ::: "memory");
        if (kt + 3 < nkt) ldA(kt + 3);

        const uint32_t st = sb + (uint32_t)(kt % 3) * STAGE;
        #pragma unroll
        for (int s16 = 0; s16 < 4; ++s16){
            uint32_t aH[4][4], aL[4][4];
            const int arow0 = (wm << 6) + (lane & 15);
            const int ahalf = lane >> 4;
            #pragma unroll
            for (int mb = 0; mb < 4; ++mb){
                int row = arow0 + (mb << 4);
                uint32_t gc = (uint32_t)(((s16 << 1) + ahalf) ^ (row & 7));
                uint32_t ad = st + (uint32_t)(row << 7) + (gc << 4);
                ldsm4(aH[mb], ad + T_AH);
                ldsm4(aL[mb], ad + T_AL);
            }
            uint32_t bH[4][2], bL[4][2];
            #pragma unroll
            for (int ng = 0; ng < 2; ++ng){
                int row = (s16 << 4) + (lane & 15);
                uint32_t nch = (uint32_t)((wn << 2) + (ng << 1) + (lane >> 4));
                uint32_t bd = st + (uint32_t)(row << 8) + ((nch ^ (uint32_t)(row & 7)) << 4);
                uint32_t rh[4], rl[4];
                ldsm4t(rh, bd + T_BH);
                ldsm4t(rl, bd + T_BL);
                bH[ng*2+0][0] = rh[0]; bH[ng*2+0][1] = rh[1];
                bH[ng*2+1][0] = rh[2]; bH[ng*2+1][1] = rh[3];
                bL[ng*2+0][0] = rl[0]; bL[ng*2+0][1] = rl[1];
                bL[ng*2+1][0] = rl[2]; bL[ng*2+1][1] = rl[3];
            }
            #pragma unroll
            for (int mb = 0; mb < 4; ++mb)
                #pragma unroll
                for (int nb = 0; nb < 4; ++nb){
                    mma16816(acc[mb][nb], aH[mb], bH[nb]);
                    mma16816(acc[mb][nb], aH[mb], bL[nb]);
                    mma16816(acc[mb][nb], aL[mb], bH[nb]);
                }
        }
    }

    const int trow = lane >> 2, tcol = (lane & 3) << 1;
    const long long cbase = (long long)zb*g.sCb + (long long)zh*g.sCh;
    #pragma unroll
    for (int mb = 0; mb < 4; ++mb){
        #pragma unroll
        for (int nb = 0; nb < 4; ++nb){
            long long r0 = m0 + (wm << 6) + (mb << 4) + trow;
            long long cc = n0 + (wn << 5) + (nb << 3) + tcol;
            float* a4 = acc[mb][nb];
            *reinterpret_cast<float2*>(g.C + cbase + r0*g.ldc + cc) = make_float2(a4[0], a4[1]);
            *reinterpret_cast<float2*>(g.C + cbase + (r0+8)*g.ldc + cc) = make_float2(a4[2], a4[3]);
        }
    }
}

// -------------- softmax over 4096 cols, in place (fp32 only) ----------------
__global__ void softmax_kernel(float* __restrict__ attn){
    __shared__ float red[256];
    const long long row = blockIdx.x;
    float* p = attn + row * 4096;
    const int t = threadIdx.x;
    float v[16];
    float mx = -3.402823466e38f;
    #pragma unroll
    for (int i = 0; i < 16; ++i){ v[i] = p[t + i*256]; mx = fmaxf(mx, v[i]); }
    red[t] = mx; __syncthreads();
    #pragma unroll
    for (int s = 128; s > 0; s >>= 1){
        if (t < s) red[t] = fmaxf(red[t], red[t + s]);
        __syncthreads();
    }
    mx = red[0]; __syncthreads();
    float sum = 0.f;
    #pragma unroll
    for (int i = 0; i < 16; ++i){ v[i] = expf(v[i] - mx); sum += v[i]; }
    red[t] = sum; __syncthreads();
    #pragma unroll
    for (int s = 128; s > 0; s >>= 1){
        if (t < s) red[t] += red[t + s];
        __syncthreads();
    }
    const float inv = 1.0f / red[0];
    #pragma unroll
    for (int i = 0; i < 16; ++i) p[t + i*256] = v[i] * inv;
}

// ---------------------------------------------------------------------------
extern "C" void kernel_launch(void* const* d_in, const int* in_sizes, int n_in,
                              void* d_out, int out_size){
    const float* vis = (const float*)d_in[0];   // [B, NV, 1024]
    const float* txt = (const float*)d_in[1];   // [B, NT, 1024]
    const float* W   = (const float*)d_in[2];   // [1024, 1024]
    float* out  = (float*)d_out;                          // [B, NT, TD]
    float* attn = out + (size_t)B_*NT_*TD_;               // [B, H, NT, NV]

    void *pVh,*pVl,*pTh,*pTl,*pWh,*pWl,*pKh,*pKl;
    cudaGetSymbolAddress(&pVh, g_Vh);  cudaGetSymbolAddress(&pVl, g_Vl);
    cudaGetSymbolAddress(&pTh, g_Th);  cudaGetSymbolAddress(&pTl, g_Tl);
    cudaGetSymbolAddress(&pWh, g_Wh);  cudaGetSymbolAddress(&pWl, g_Wl);
    cudaGetSymbolAddress(&pKh, g_Kh);  cudaGetSymbolAddress(&pKl, g_Kl);

    cudaFuncSetAttribute(gemm256,
                         cudaFuncAttributeMaxDynamicSharedMemorySize, SMEM_G2);
    cudaFuncSetAttribute(gemm_transb,
                         cudaFuncAttributeMaxDynamicSharedMemorySize, SMEM_GEMM);

    // Split inputs to bf16 hi/lo
    split_kernel<<<8192, 256>>>(vis, (__nv_bfloat16*)pVh, (__nv_bfloat16*)pVl, (long long)B_*NV_*TD_/4);
    split_kernel<<<4096, 256>>>(txt, (__nv_bfloat16*)pTh, (__nv_bfloat16*)pTl, (long long)B_*NT_*TD_/4);
    split_kernel<<<1024, 256>>>(W,   (__nv_bfloat16*)pWh, (__nv_bfloat16*)pWl, (long long)TD_*TD_/4);

    // GEMM1: k = visual @ W^T -> bf16 hi/lo   (M=16384, N=1024, K=1024)
    GemmArgs a1{};
    a1.Ah = (const __nv_bfloat16*)pVh; a1.Al = (const __nv_bfloat16*)pVl;
    a1.Bh = (const __nv_bfloat16*)pWh; a1.Bl = (const __nv_bfloat16*)pWl;
    a1.Ch = (__nv_bfloat16*)pKh; a1.Cl = (__nv_bfloat16*)pKl;
    a1.lda = 1024; a1.ldb = 1024; a1.ldc = 1024;
    a1.K = 1024; a1.HZ = 1;
    gemm256<<<dim3(64, 8, 1), 256, SMEM_G2>>>(a1);

    // GEMM2: sim = q . k  (per z=(b,h): M=1024, N=4096, K=128)
    GemmArgs a2{};
    a2.Ah = (const __nv_bfloat16*)pTh; a2.Al = (const __nv_bfloat16*)pTl;
    a2.Bh = (const __nv_bfloat16*)pKh; a2.Bl = (const __nv_bfloat16*)pKl;
    a2.C = attn;
    a2.lda = 1024; a2.ldb = 1024; a2.ldc = 4096;
    a2.sAb = (long long)NT_*TD_;    a2.sAh = 128;
    a2.sBb = (long long)NV_*TD_;    a2.sBh = 128;
    a2.sCb = (long long)H_*NT_*NV_; a2.sCh = (long long)NT_*NV_;
    a2.K = 128; a2.HZ = 8;
    gemm256<<<dim3(4, 32, 32), 256, SMEM_G2>>>(a2);

    // Softmax in place (fp32 attn is both an output and GEMM3's A)
    softmax_kernel<<<B_*H_*NT_, 256>>>(attn);

    // GEMM3: out = attn @ k  (per z=(b,h): M=1024, N=128, K=4096)
    GemmArgs a3{};
    a3.Af32 = attn;
    a3.Bh = (const __nv_bfloat16*)pKh; a3.Bl = (const __nv_bfloat16*)pKl;
    a3.C = out;
    a3.lda = 4096; a3.ldb = 1024; a3.ldc = 1024;
    a3.sAb = (long long)H_*NT_*NV_; a3.sAh = (long long)NT_*NV_;
    a3.sBb = (long long)NV_*TD_;    a3.sBh = 128;
    a3.sCb = (long long)NT_*TD_;    a3.sCh = 128;
    a3.K = 4096; a3.HZ = 8;
    gemm_transb<<<dim3(8, 1, 32), 256, SMEM_GEMM>>>(a3);
}

// round 7
// speedup vs baseline: 1.0004x; 1.0004x over previous
#include <cuda_runtime.h>
#include <cuda_bf16.h>
#include <cstdint>

#define B_  4
#define NV_ 4096
#define NT_ 1024
#define TD_ 1024
#define H_  8
#define D_  128

// ------------------------- scratch (device globals) -------------------------
__device__ __align__(256) __nv_bfloat16 g_Vh[(size_t)B_*NV_*TD_];
__device__ __align__(256) __nv_bfloat16 g_Vl[(size_t)B_*NV_*TD_];
__device__ __align__(256) __nv_bfloat16 g_Th[(size_t)B_*NT_*TD_];
__device__ __align__(256) __nv_bfloat16 g_Tl[(size_t)B_*NT_*TD_];
__device__ __align__(256) __nv_bfloat16 g_Wh[(size_t)TD_*TD_];
__device__ __align__(256) __nv_bfloat16 g_Wl[(size_t)TD_*TD_];
__device__ __align__(256) __nv_bfloat16 g_Kh[(size_t)B_*NV_*TD_];
__device__ __align__(256) __nv_bfloat16 g_Kl[(size_t)B_*NV_*TD_];

// ------------------------------- helpers ------------------------------------
__device__ __forceinline__ uint32_t smem_u32(const void* p){
    uint32_t a;
    asm("{ .reg .u64 t; cvta.to.shared.u64 t, %1; cvt.u32.u64 %0, t; }" : "=r"(a) : "l"(p));
    return a;
}
__device__ __forceinline__ void cp16(uint32_t dst, const void* src){
    asm volatile("cp.async.cg.shared.global [%0], [%1], 16;" :: "r"(dst), "l"(src));
}
__device__ __forceinline__ void ldsm4(uint32_t* r, uint32_t addr){
    asm volatile("ldmatrix.sync.aligned.m8n8.x4.shared.b16 {%0,%1,%2,%3}, [%4];"
                 : "=r"(r[0]), "=r"(r[1]), "=r"(r[2]), "=r"(r[3]) : "r"(addr));
}
__device__ __forceinline__ void ldsm4t(uint32_t* r, uint32_t addr){
    asm volatile("ldmatrix.sync.aligned.m8n8.x4.trans.shared.b16 {%0,%1,%2,%3}, [%4];"
                 : "=r"(r[0]), "=r"(r[1]), "=r"(r[2]), "=r"(r[3]) : "r"(addr));
}
__device__ __forceinline__ void mma16816(float* c, const uint32_t* a, const uint32_t* b){
    asm volatile("mma.sync.aligned.m16n8k16.row.col.f32.bf16.bf16.f32 "
                 "{%0,%1,%2,%3}, {%4,%5,%6,%7}, {%8,%9}, {%0,%1,%2,%3};"
                 : "+f"(c[0]), "+f"(c[1]), "+f"(c[2]), "+f"(c[3])
                 : "r"(a[0]), "r"(a[1]), "r"(a[2]), "r"(a[3]), "r"(b[0]), "r"(b[1]));
}
__device__ __forceinline__ void split2(float x, float y, uint32_t& hp, uint32_t& lp){
    __nv_bfloat16 h0 = __float2bfloat16(x), h1 = __float2bfloat16(y);
    __nv_bfloat16 l0 = __float2bfloat16(x - __bfloat162float(h0));
    __nv_bfloat16 l1 = __float2bfloat16(y - __bfloat162float(h1));
    hp = (uint32_t)__bfloat16_as_ushort(h0) | ((uint32_t)__bfloat16_as_ushort(h1) << 16);
    lp = (uint32_t)__bfloat16_as_ushort(l0) | ((uint32_t)__bfloat16_as_ushort(l1) << 16);
}

// ------------------------- fp32 -> bf16 hi/lo split --------------------------
__global__ void split_kernel(const float* __restrict__ s, __nv_bfloat16* __restrict__ h,
                             __nv_bfloat16* __restrict__ l, long long n4){
    long long i = (long long)blockIdx.x * blockDim.x + threadIdx.x;
    long long stride = (long long)gridDim.x * blockDim.x;
    for (; i < n4; i += stride){
        float4 f = reinterpret_cast<const float4*>(s)[i];
        uint32_t h0, l0, h1, l1;
        split2(f.x, f.y, h0, l0);
        split2(f.z, f.w, h1, l1);
        reinterpret_cast<uint2*>(h)[i] = make_uint2(h0, h1);
        reinterpret_cast<uint2*>(l)[i] = make_uint2(l0, l1);
    }
}

struct GemmArgs {
    const __nv_bfloat16 *Ah, *Al, *Bh, *Bl;
    const float* Af32;
    float* C; __nv_bfloat16 *Ch, *Cl;
    long long lda, ldb, ldc;
    long long sAb, sAh, sBb, sBh, sCb, sCh;
    int K, HZ;
};

// ---------------------------------------------------------------------------
// 256x128 CTA-tile split-3 GEMM (K-major A and B, pre-split bf16 pairs).
// 8 warps as 4m x 2n, warp tile 64x64. K-chunk 64, 2-stage cp.async ring.
// Inner loop keeps only one B ldsm-pair live -> ~195 regs, no spills.
// ---------------------------------------------------------------------------
#define G2_AH 0
#define G2_AL 32768
#define G2_BH 65536
#define G2_BL 81920
#define G2_STAGE 98304
#define SMEM_G2 (2*G2_STAGE)

__global__ void __launch_bounds__(256, 1) gemm256(GemmArgs g){
    extern __shared__ char smem[];
    const uint32_t sb = smem_u32(smem);
    const int tid = threadIdx.x;
    const int lane = tid & 31, wid = tid >> 5;
    const int wm = wid >> 1, wn = wid & 1;

    const int zb = blockIdx.z / g.HZ, zh = blockIdx.z % g.HZ;
    const long long m0 = (long long)blockIdx.x << 8;
    const long long n0 = (long long)blockIdx.y << 7;
    const long long aoff = (long long)zb*g.sAb + (long long)zh*g.sAh + m0*g.lda;
    const __nv_bfloat16* Ah = g.Ah + aoff;
    const __nv_bfloat16* Al = g.Al + aoff;
    const long long boff = (long long)zb*g.sBb + (long long)zh*g.sBh + n0*g.ldb;
    const __nv_bfloat16* Bh = g.Bh + boff;
    const __nv_bfloat16* Bl = g.Bl + boff;

    float acc[4][8][4];
    #pragma unroll
    for (int a = 0; a < 4; ++a)
        #pragma unroll
        for (int b = 0; b < 8; ++b)
            #pragma unroll
            for (int c = 0; c < 4; ++c) acc[a][b][c] = 0.f;

    const int nkt = g.K >> 6;

    auto load_stage = [&](int S, int kt2){
        const uint32_t sbs = sb + (uint32_t)S * G2_STAGE;
        const long long K0 = (long long)kt2 << 6;
        const int r0 = tid >> 3, gc = tid & 7;
        #pragma unroll
        for (int i = 0; i < 8; ++i){               // A: 256 rows
            int row = r0 + (i << 5);
            uint32_t off = (uint32_t)(row << 7) + (uint32_t)((gc ^ (row & 7)) << 4);
            long long ea = (long long)row * g.lda + K0 + (gc << 3);
            cp16(sbs + G2_AH + off, Ah + ea);
            cp16(sbs + G2_AL + off, Al + ea);
        }
        #pragma unroll
        for (int i = 0; i < 4; ++i){               // B: 128 rows
            int row = r0 + (i << 5);
            uint32_t off = (uint32_t)(row << 7) + (uint32_t)((gc ^ (row & 7)) << 4);
            long long eb = (long long)row * g.ldb + K0 + (gc << 3);
            cp16(sbs + G2_BH + off, Bh + eb);
            cp16(sbs + G2_BL + off, Bl + eb);
        }
    };

    load_stage(0, 0);
    asm volatile("cp.async.commit_group;" ::: "memory");

    for (int kt = 0; kt < nkt; ++kt){
        if (kt + 1 < nkt) load_stage((kt + 1) & 1, kt + 1);
        asm volatile("cp.async.commit_group;" ::: "memory");
        asm volatile("cp.async.wait_group 1;" ::: "memory");
        __syncthreads();

        const uint32_t st = sb + (uint32_t)(kt & 1) * G2_STAGE;
        #pragma unroll
        for (int s16 = 0; s16 < 4; ++s16){
            uint32_t aH[4][4], aL[4][4];
            const int arow0 = (wm << 6) + (lane & 15);
            const int ahalf = lane >> 4;
            #pragma unroll
            for (int mb = 0; mb < 4; ++mb){
                int row = arow0 + (mb << 4);
                uint32_t gc = (uint32_t)(((s16 << 1) + ahalf) ^ (row & 7));
                uint32_t ad = st + (uint32_t)(row << 7) + (gc << 4);
                ldsm4(aH[mb], ad + G2_AH);
                ldsm4(aL[mb], ad + G2_AL);
            }
            // One B ldsm-pair live at a time: 2 LDSM -> 24 HMMA per group
            const int brow_ = (lane & 7) + ((lane >> 4) << 3);
            const int bhalf = (lane >> 3) & 1;
            #pragma unroll
            for (int bg = 0; bg < 4; ++bg){
                int row = (wn << 6) + (bg << 4) + brow_;
                uint32_t gc = (uint32_t)(((s16 << 1) + bhalf) ^ (row & 7));
                uint32_t bd = st + (uint32_t)(row << 7) + (gc << 4);
                uint32_t rh[4], rl[4];
                ldsm4(rh, bd + G2_BH);
                ldsm4(rl, bd + G2_BL);
                uint32_t b0h[2] = {rh[0], rh[1]}, b1h[2] = {rh[2], rh[3]};
                uint32_t b0l[2] = {rl[0], rl[1]}, b1l[2] = {rl[2], rl[3]};
                #pragma unroll
                for (int mb = 0; mb < 4; ++mb){
                    mma16816(acc[mb][2*bg],   aH[mb], b0h);
                    mma16816(acc[mb][2*bg],   aH[mb], b0l);
                    mma16816(acc[mb][2*bg],   aL[mb], b0h);
                    mma16816(acc[mb][2*bg+1], aH[mb], b1h);
                    mma16816(acc[mb][2*bg+1], aH[mb], b1l);
                    mma16816(acc[mb][2*bg+1], aL[mb], b1h);
                }
            }
        }
        __syncthreads();
    }

    // ---- epilogue ----
    const int trow = lane >> 2, tcol = (lane & 3) << 1;
    const long long cbase = (long long)zb*g.sCb + (long long)zh*g.sCh;
    #pragma unroll
    for (int mb = 0; mb < 4; ++mb){
        #pragma unroll
        for (int nb = 0; nb < 8; ++nb){
            long long r0 = m0 + (wm << 6) + (mb << 4) + trow;
            long long cc = n0 + (wn << 6) + (nb << 3) + tcol;
            float* a4 = acc[mb][nb];
            if (g.C){
                *reinterpret_cast<float2*>(g.C + cbase + r0*g.ldc + cc) = make_float2(a4[0], a4[1]);
                *reinterpret_cast<float2*>(g.C + cbase + (r0+8)*g.ldc + cc) = make_float2(a4[2], a4[3]);
            } else {
                uint32_t hp, lp;
                split2(a4[0], a4[1], hp, lp);
                *reinterpret_cast<uint32_t*>(g.Ch + cbase + r0*g.ldc + cc) = hp;
                *reinterpret_cast<uint32_t*>(g.Cl + cbase + r0*g.ldc + cc) = lp;
                split2(a4[2], a4[3], hp, lp);
                *reinterpret_cast<uint32_t*>(g.Ch + cbase + (r0+8)*g.ldc + cc) = hp;
                *reinterpret_cast<uint32_t*>(g.Cl + cbase + (r0+8)*g.ldc + cc) = lp;
            }
        }
    }
}

// ---------------------------------------------------------------------------
// 128x128 TRANSB kernel (GEMM3): A fp32 split on the fly, B N-major via
// ldmatrix.trans. 8 warps 2m x 4n, warp tile 64x32, 3-stage ring.
// ---------------------------------------------------------------------------
#define T_AH 0
#define T_AL 16384
#define T_BH 32768
#define T_BL 49152
#define STAGE 65536
#define SMEM_GEMM (3*STAGE)

__global__ void __launch_bounds__(256, 1) gemm_transb(GemmArgs g){
    extern __shared__ char smem[];
    const uint32_t sb = smem_u32(smem);
    const int tid = threadIdx.x;
    const int lane = tid & 31, wid = tid >> 5;
    const int wm = wid >> 2, wn = wid & 3;

    const int zb = blockIdx.z / g.HZ, zh = blockIdx.z % g.HZ;
    const long long m0 = (long long)blockIdx.x << 7;
    const long long n0 = (long long)blockIdx.y << 7;
    const long long aoff = (long long)zb*g.sAb + (long long)zh*g.sAh + m0*g.lda;
    const float* Af32 = g.Af32 + aoff;
    const long long bofs = (long long)zb*g.sBb + (long long)zh*g.sBh + n0;
    const __nv_bfloat16* Bh = g.Bh + bofs;
    const __nv_bfloat16* Bl = g.Bl + bofs;

    float acc[4][4][4];
    #pragma unroll
    for (int a = 0; a < 4; ++a)
        #pragma unroll
        for (int b = 0; b < 4; ++b)
            #pragma unroll
            for (int c = 0; c < 4; ++c) acc[a][b][c] = 0.f;

    const int nkt = g.K >> 6;

    auto loadB = [&](int S, int kt2){
        const uint32_t sbs = sb + (uint32_t)S * STAGE;
        const long long K0 = (long long)kt2 << 6;
        const int r0 = tid >> 4, bc = tid & 15;
        #pragma unroll
        for (int i = 0; i < 4; ++i){
            int row = r0 + (i << 4);
            uint32_t off = (uint32_t)(row << 8) + (uint32_t)((bc ^ (row & 7)) << 4);
            long long eb = (K0 + row) * g.ldb + (bc << 3);
            cp16(sbs + T_BH + off, Bh + eb);
            cp16(sbs + T_BL + off, Bl + eb);
        }
    };
    float4 ra[8];
    auto ldA = [&](int kt2){
        const long long K0 = (long long)kt2 << 6;
        #pragma unroll
        for (int i = 0; i < 8; ++i){
            int lin = tid + (i << 8);
            int row = lin >> 4, c4 = lin & 15;
            ra[i] = *reinterpret_cast<const float4*>(Af32 + (long long)row*g.lda + K0 + (c4 << 2));
        }
    };
    auto stA = [&](int S){
        char* base = smem + (size_t)S * STAGE;
        #pragma unroll
        for (int i = 0; i < 8; ++i){
            int lin = tid + (i << 8);
            int row = lin >> 4, c4 = lin & 15;
            uint32_t h0, l0, h1, l1;
            split2(ra[i].x, ra[i].y, h0, l0);
            split2(ra[i].z, ra[i].w, h1, l1);
            uint32_t off = (uint32_t)(row << 7)
                         + ((uint32_t)((c4 >> 1) ^ (row & 7)) << 4)
                         + ((uint32_t)(c4 & 1) << 3);
            *reinterpret_cast<uint2*>(base + T_AH + off) = make_uint2(h0, h1);
            *reinterpret_cast<uint2*>(base + T_AL + off) = make_uint2(l0, l1);
        }
    };

    ldA(0); stA(0); loadB(0, 0);
    asm volatile("cp.async.commit_group;" ::: "memory");
    if (nkt > 1){ ldA(1); stA(1); loadB(1, 1); }
    asm volatile("cp.async.commit_group;" ::: "memory");
    if (nkt > 2) ldA(2);

    for (int kt = 0; kt < nkt; ++kt){
        asm volatile("cp.async.wait_group 1;" ::: "memory");
        __syncthreads();
        if (kt + 2 < nkt){ stA((kt + 2) % 3); loadB((kt + 2) % 3, kt + 2); }
        asm volatile("cp.async.commit_group;" ::: "memory");
        if (kt + 3 < nkt) ldA(kt + 3);

        const uint32_t st = sb + (uint32_t)(kt % 3) * STAGE;
        #pragma unroll
        for (int s16 = 0; s16 < 4; ++s16){
            uint32_t aH[4][4], aL[4][4];
            const int arow0 = (wm << 6) + (lane & 15);
            const int ahalf = lane >> 4;
            #pragma unroll
            for (int mb = 0; mb < 4; ++mb){
                int row = arow0 + (mb << 4);
                uint32_t gc = (uint32_t)(((s16 << 1) + ahalf) ^ (row & 7));
                uint32_t ad = st + (uint32_t)(row << 7) + (gc << 4);
                ldsm4(aH[mb], ad + T_AH);
                ldsm4(aL[mb], ad + T_AL);
            }
            uint32_t bH[4][2], bL[4][2];
            #pragma unroll
            for (int ng = 0; ng < 2; ++ng){
                int row = (s16 << 4) + (lane & 15);
                uint32_t nch = (uint32_t)((wn << 2) + (ng << 1) + (lane >> 4));
                uint32_t bd = st + (uint32_t)(row << 8) + ((nch ^ (uint32_t)(row & 7)) << 4);
                uint32_t rh[4], rl[4];
                ldsm4t(rh, bd + T_BH);
                ldsm4t(rl, bd + T_BL);
                bH[ng*2+0][0] = rh[0]; bH[ng*2+0][1] = rh[1];
                bH[ng*2+1][0] = rh[2]; bH[ng*2+1][1] = rh[3];
                bL[ng*2+0][0] = rl[0]; bL[ng*2+0][1] = rl[1];
                bL[ng*2+1][0] = rl[2]; bL[ng*2+1][1] = rl[3];
            }
            #pragma unroll
            for (int mb = 0; mb < 4; ++mb)
                #pragma unroll
                for (int nb = 0; nb < 4; ++nb){
                    mma16816(acc[mb][nb], aH[mb], bH[nb]);
                    mma16816(acc[mb][nb], aH[mb], bL[nb]);
                    mma16816(acc[mb][nb], aL[mb], bH[nb]);
                }
        }
    }

    const int trow = lane >> 2, tcol = (lane & 3) << 1;
    const long long cbase = (long long)zb*g.sCb + (long long)zh*g.sCh;
    #pragma unroll
    for (int mb = 0; mb < 4; ++mb){
        #pragma unroll
        for (int nb = 0; nb < 4; ++nb){
            long long r0 = m0 + (wm << 6) + (mb << 4) + trow;
            long long cc = n0 + (wn << 5) + (nb << 3) + tcol;
            float* a4 = acc[mb][nb];
            *reinterpret_cast<float2*>(g.C + cbase + r0*g.ldc + cc) = make_float2(a4[0], a4[1]);
            *reinterpret_cast<float2*>(g.C + cbase + (r0+8)*g.ldc + cc) = make_float2(a4[2], a4[3]);
        }
    }
}

// -------------- softmax over 4096 cols, in place (fp32 only) ----------------
__global__ void softmax_kernel(float* __restrict__ attn){
    __shared__ float red[256];
    const long long row = blockIdx.x;
    float* p = attn + row * 4096;
    const int t = threadIdx.x;
    float v[16];
    float mx = -3.402823466e38f;
    #pragma unroll
    for (int i = 0; i < 16; ++i){ v[i] = p[t + i*256]; mx = fmaxf(mx, v[i]); }
    red[t] = mx; __syncthreads();
    #pragma unroll
    for (int s = 128; s > 0; s >>= 1){
        if (t < s) red[t] = fmaxf(red[t], red[t + s]);
        __syncthreads();
    }
    mx = red[0]; __syncthreads();
    float sum = 0.f;
    #pragma unroll
    for (int i = 0; i < 16; ++i){ v[i] = __expf(v[i] - mx); sum += v[i]; }
    red[t] = sum; __syncthreads();
    #pragma unroll
    for (int s = 128; s > 0; s >>= 1){
        if (t < s) red[t] += red[t + s];
        __syncthreads();
    }
    const float inv = 1.0f / red[0];
    #pragma unroll
    for (int i = 0; i < 16; ++i) p[t + i*256] = v[i] * inv;
}

// ---------------------------------------------------------------------------
extern "C" void kernel_launch(void* const* d_in, const int* in_sizes, int n_in,
                              void* d_out, int out_size){
    const float* vis = (const float*)d_in[0];   // [B, NV, 1024]
    const float* txt = (const float*)d_in[1];   // [B, NT, 1024]
    const float* W   = (const float*)d_in[2];   // [1024, 1024]
    float* out  = (float*)d_out;                          // [B, NT, TD]
    float* attn = out + (size_t)B_*NT_*TD_;               // [B, H, NT, NV]

    void *pVh,*pVl,*pTh,*pTl,*pWh,*pWl,*pKh,*pKl;
    cudaGetSymbolAddress(&pVh, g_Vh);  cudaGetSymbolAddress(&pVl, g_Vl);
    cudaGetSymbolAddress(&pTh, g_Th);  cudaGetSymbolAddress(&pTl, g_Tl);
    cudaGetSymbolAddress(&pWh, g_Wh);  cudaGetSymbolAddress(&pWl, g_Wl);
    cudaGetSymbolAddress(&pKh, g_Kh);  cudaGetSymbolAddress(&pKl, g_Kl);

    cudaFuncSetAttribute(gemm256,
                         cudaFuncAttributeMaxDynamicSharedMemorySize, SMEM_G2);
    cudaFuncSetAttribute(gemm_transb,
                         cudaFuncAttributeMaxDynamicSharedMemorySize, SMEM_GEMM);

    // Split inputs to bf16 hi/lo
    split_kernel<<<8192, 256>>>(vis, (__nv_bfloat16*)pVh, (__nv_bfloat16*)pVl, (long long)B_*NV_*TD_/4);
    split_kernel<<<4096, 256>>>(txt, (__nv_bfloat16*)pTh, (__nv_bfloat16*)pTl, (long long)B_*NT_*TD_/4);
    split_kernel<<<1024, 256>>>(W,   (__nv_bfloat16*)pWh, (__nv_bfloat16*)pWl, (long long)TD_*TD_/4);

    // GEMM1: k = visual @ W^T -> bf16 hi/lo   (M=16384, N=1024, K=1024)
    GemmArgs a1{};
    a1.Ah = (const __nv_bfloat16*)pVh; a1.Al = (const __nv_bfloat16*)pVl;
    a1.Bh = (const __nv_bfloat16*)pWh; a1.Bl = (const __nv_bfloat16*)pWl;
    a1.Ch = (__nv_bfloat16*)pKh; a1.Cl = (__nv_bfloat16*)pKl;
    a1.lda = 1024; a1.ldb = 1024; a1.ldc = 1024;
    a1.K = 1024; a1.HZ = 1;
    gemm256<<<dim3(64, 8, 1), 256, SMEM_G2>>>(a1);

    // GEMM2: sim = q . k  (per z=(b,h): M=1024, N=4096, K=128)
    GemmArgs a2{};
    a2.Ah = (const __nv_bfloat16*)pTh; a2.Al = (const __nv_bfloat16*)pTl;
    a2.Bh = (const __nv_bfloat16*)pKh; a2.Bl = (const __nv_bfloat16*)pKl;
    a2.C = attn;
    a2.lda = 1024; a2.ldb = 1024; a2.ldc = 4096;
    a2.sAb = (long long)NT_*TD_;    a2.sAh = 128;
    a2.sBb = (long long)NV_*TD_;    a2.sBh = 128;
    a2.sCb = (long long)H_*NT_*NV_; a2.sCh = (long long)NT_*NV_;
    a2.K = 128; a2.HZ = 8;
    gemm256<<<dim3(4, 32, 32), 256, SMEM_G2>>>(a2);

    // Softmax in place (fp32 attn is both an output and GEMM3's A)
    softmax_kernel<<<B_*H_*NT_, 256>>>(attn);

    // GEMM3: out = attn @ k  (per z=(b,h): M=1024, N=128, K=4096)
    GemmArgs a3{};
    a3.Af32 = attn;
    a3.Bh = (const __nv_bfloat16*)pKh; a3.Bl = (const __nv_bfloat16*)pKl;
    a3.C = out;
    a3.lda = 4096; a3.ldb = 1024; a3.ldc = 1024;
    a3.sAb = (long long)H_*NT_*NV_; a3.sAh = (long long)NT_*NV_;
    a3.sBb = (long long)NV_*TD_;    a3.sBh = 128;
    a3.sCb = (long long)NT_*TD_;    a3.sCh = 128;
    a3.K = 4096; a3.HZ = 8;
    gemm_transb<<<dim3(8, 1, 32), 256, SMEM_GEMM>>>(a3);
}